// round 1
// baseline (speedup 1.0000x reference)
#include <cuda_runtime.h>

// Problem constants
#define Bq    8
#define Nq    4096
#define Cq    1024
#define ICq   256
#define ROWS  (Bq * Nq)      // 32768
#define EPSq  1e-5f

// ---------------------------------------------------------------------------
// Scratch (static device globals — no allocation in kernel_launch)
// ---------------------------------------------------------------------------
__device__ float g_Theta[ROWS * ICq];      // 32 MB
__device__ float g_Phi[ROWS * ICq];        // 32 MB
__device__ float g_G[ROWS * ICq];          // 32 MB
__device__ float g_M[Bq * ICq * ICq];      // 2 MB   M_b[i][j] = sum_n Phi[n][i]G[n][j]/N
__device__ float g_Q[Bq * Cq * ICq];       // 8 MB   Q_b[c][i] = sum_j M_b[i][j] W_w[c][j]
__device__ float g_sum[Cq];
__device__ float g_sumsq[Cq];

// ---------------------------------------------------------------------------
// Zero the atomic-accumulated scratch
// ---------------------------------------------------------------------------
__global__ void zero_scratch() {
    int i = blockIdx.x * blockDim.x + threadIdx.x;
    if (i < Bq * ICq * ICq) g_M[i] = 0.f;
    if (i < Cq) { g_sum[i] = 0.f; g_sumsq[i] = 0.f; }
}

// ---------------------------------------------------------------------------
// Generic NT SGEMM:  C[m][n] = alpha * sum_k A[m][k] * B[n][k]  (+ bias[n])
// A: M x K row-major, B: N x K row-major, C: M x N row-major.
// Batched via blockIdx.z with element strides sA, sB, sC.
// Requires M % 128 == 0, N % 128 == 0, K % 16 == 0.
// Block: 256 threads; 128x128 tile, BK=16, 8x8 per thread.
// ---------------------------------------------------------------------------
__global__ __launch_bounds__(256)
void sgemm_nt(const float* __restrict__ A, long long sA,
              const float* __restrict__ B, long long sB,
              const float* __restrict__ bias,
              float* __restrict__ C, long long sC,
              int M, int N, int K, float alpha)
{
    const int BM = 128, BN = 128, BK = 16, TM = 8, TN = 8;
    __shared__ float As[BK][BM];
    __shared__ float Bs[BK][BN];

    const long long b = blockIdx.z;
    A += b * sA;
    B += b * sB;
    C += b * sC;

    const int mBlock = blockIdx.y * BM;
    const int nBlock = blockIdx.x * BN;
    const int tid = threadIdx.x;

    // Loader mapping: 4 float4 per K-row -> ldRow in [0,64), two row passes
    const int ldRow = tid >> 2;            // 0..63
    const int ldCol = (tid & 3) * 4;       // 0,4,8,12

    // Compute mapping
    const int tRow = (tid / (BN / TN)) * TM;   // (tid/16)*8
    const int tCol = (tid % (BN / TN)) * TN;   // (tid%16)*8

    float acc[TM][TN];
    #pragma unroll
    for (int i = 0; i < TM; i++)
        #pragma unroll
        for (int j = 0; j < TN; j++) acc[i][j] = 0.f;

    float regM[TM], regN[TN];

    for (int k0 = 0; k0 < K; k0 += BK) {
        #pragma unroll
        for (int r = 0; r < BM; r += 64) {
            float4 t = *reinterpret_cast<const float4*>(
                &A[(long long)(mBlock + ldRow + r) * K + k0 + ldCol]);
            As[ldCol + 0][ldRow + r] = t.x;
            As[ldCol + 1][ldRow + r] = t.y;
            As[ldCol + 2][ldRow + r] = t.z;
            As[ldCol + 3][ldRow + r] = t.w;
        }
        #pragma unroll
        for (int r = 0; r < BN; r += 64) {
            float4 t = *reinterpret_cast<const float4*>(
                &B[(long long)(nBlock + ldRow + r) * K + k0 + ldCol]);
            Bs[ldCol + 0][ldRow + r] = t.x;
            Bs[ldCol + 1][ldRow + r] = t.y;
            Bs[ldCol + 2][ldRow + r] = t.z;
            Bs[ldCol + 3][ldRow + r] = t.w;
        }
        __syncthreads();

        #pragma unroll
        for (int kk = 0; kk < BK; kk++) {
            #pragma unroll
            for (int i = 0; i < TM; i++) regM[i] = As[kk][tRow + i];
            #pragma unroll
            for (int j = 0; j < TN; j++) regN[j] = Bs[kk][tCol + j];
            #pragma unroll
            for (int i = 0; i < TM; i++)
                #pragma unroll
                for (int j = 0; j < TN; j++)
                    acc[i][j] += regM[i] * regN[j];
        }
        __syncthreads();
    }

    #pragma unroll
    for (int i = 0; i < TM; i++) {
        #pragma unroll
        for (int j = 0; j < TN; j += 4) {
            float4 o;
            float b0 = bias ? bias[nBlock + tCol + j + 0] : 0.f;
            float b1 = bias ? bias[nBlock + tCol + j + 1] : 0.f;
            float b2 = bias ? bias[nBlock + tCol + j + 2] : 0.f;
            float b3 = bias ? bias[nBlock + tCol + j + 3] : 0.f;
            o.x = alpha * acc[i][j + 0] + b0;
            o.y = alpha * acc[i][j + 1] + b1;
            o.z = alpha * acc[i][j + 2] + b2;
            o.w = alpha * acc[i][j + 3] + b3;
            *reinterpret_cast<float4*>(
                &C[(long long)(mBlock + tRow + i) * N + nBlock + tCol + j]) = o;
        }
    }
}

// ---------------------------------------------------------------------------
// M_b[i][j] = (1/N) * sum_n Phi_b[n][i] * G_b[n][j]
// Split-K over n (32 chunks of 128 rows), atomicAdd into g_M (pre-zeroed).
// Grid: (IC/64, IC/64, B*32). Block: 256 threads; 64x64 tile, 4x4 per thread.
// ---------------------------------------------------------------------------
__global__ __launch_bounds__(256)
void phiTg_kernel(const float* __restrict__ Phi, const float* __restrict__ G)
{
    const int NS = 32, CH = Nq / NS;   // 128 rows per chunk
    const int bz    = blockIdx.z;
    const int batch = bz / NS;
    const int chunk = bz % NS;

    const float* Pb = Phi + (long long)batch * Nq * ICq + (long long)chunk * CH * ICq;
    const float* Gb = G   + (long long)batch * Nq * ICq + (long long)chunk * CH * ICq;

    __shared__ float Ps[8][64];
    __shared__ float Gs[8][64];

    const int i0 = blockIdx.x * 64;
    const int j0 = blockIdx.y * 64;
    const int tid = threadIdx.x;

    // Loader: 8x64 tile = 128 float4; tid<128 -> Phi, tid>=128 -> G
    const int lt = tid & 127;
    const int ln = lt >> 4;          // 0..7 (n within tile)
    const int lc = (lt & 15) * 4;    // 0..60

    // Compute: (i,j) tile: 4x4 per thread
    const int ti = (tid & 15) * 4;
    const int tj = (tid >> 4) * 4;

    float acc[4][4] = {{0.f}};

    for (int n0 = 0; n0 < CH; n0 += 8) {
        if (tid < 128) {
            float4 t = *reinterpret_cast<const float4*>(
                &Pb[(long long)(n0 + ln) * ICq + i0 + lc]);
            Ps[ln][lc + 0] = t.x; Ps[ln][lc + 1] = t.y;
            Ps[ln][lc + 2] = t.z; Ps[ln][lc + 3] = t.w;
        } else {
            float4 t = *reinterpret_cast<const float4*>(
                &Gb[(long long)(n0 + ln) * ICq + j0 + lc]);
            Gs[ln][lc + 0] = t.x; Gs[ln][lc + 1] = t.y;
            Gs[ln][lc + 2] = t.z; Gs[ln][lc + 3] = t.w;
        }
        __syncthreads();

        #pragma unroll
        for (int kk = 0; kk < 8; kk++) {
            float pi[4], gj[4];
            #pragma unroll
            for (int a = 0; a < 4; a++) pi[a] = Ps[kk][ti + a];
            #pragma unroll
            for (int a = 0; a < 4; a++) gj[a] = Gs[kk][tj + a];
            #pragma unroll
            for (int a = 0; a < 4; a++)
                #pragma unroll
                for (int c = 0; c < 4; c++)
                    acc[a][c] += pi[a] * gj[c];
        }
        __syncthreads();
    }

    float* Mb = g_M + (long long)batch * ICq * ICq;
    const float scale = 1.f / (float)Nq;
    #pragma unroll
    for (int a = 0; a < 4; a++)
        #pragma unroll
        for (int c = 0; c < 4; c++)
            atomicAdd(&Mb[(long long)(i0 + ti + a) * ICq + (j0 + tj + c)],
                      acc[a][c] * scale);
}

// ---------------------------------------------------------------------------
// Per-channel sum / sumsq over (B*N) rows of W_y (= d_out before BN).
// Grid: (C/128, 128). Block: 128. Each thread: one channel, 256 rows.
// ---------------------------------------------------------------------------
__global__ __launch_bounds__(128)
void bn_stats(const float* __restrict__ Wy)
{
    const int ch = blockIdx.x * 128 + threadIdx.x;
    const long long r0 = (long long)blockIdx.y * 256;
    const float* p = Wy + r0 * Cq + ch;
    float s = 0.f, s2 = 0.f;
    #pragma unroll 8
    for (int r = 0; r < 256; r++) {
        float x = p[(long long)r * Cq];
        s  += x;
        s2 += x * x;
    }
    atomicAdd(&g_sum[ch], s);
    atomicAdd(&g_sumsq[ch], s2);
}

// ---------------------------------------------------------------------------
// out = (W_y - mean) * rsqrt(var+eps) * gamma + beta + v   (in place on d_out)
// ---------------------------------------------------------------------------
__global__ __launch_bounds__(256)
void bn_finalize(float* __restrict__ out, const float* __restrict__ v,
                 const float* __restrict__ gamma, const float* __restrict__ beta)
{
    const long long i4 = (long long)blockIdx.x * 256 + threadIdx.x;  // float4 index
    const int c4 = (int)(i4 & (Cq / 4 - 1)) * 4;
    float4 w  = reinterpret_cast<float4*>(out)[i4];
    float4 vv = reinterpret_cast<const float4*>(v)[i4];
    const float inv = 1.f / (float)ROWS;
    float* wp = &w.x;
    const float* vp = &vv.x;
    #pragma unroll
    for (int c = 0; c < 4; c++) {
        float mean = g_sum[c4 + c] * inv;
        float var  = g_sumsq[c4 + c] * inv - mean * mean;
        float sc   = gamma[c4 + c] * rsqrtf(var + EPSq);
        wp[c] = (wp[c] - mean) * sc + beta[c4 + c] + vp[c];
    }
    reinterpret_cast<float4*>(out)[i4] = w;
}

// ---------------------------------------------------------------------------
// Launch
// ---------------------------------------------------------------------------
extern "C" void kernel_launch(void* const* d_in, const int* in_sizes, int n_in,
                              void* d_out, int out_size)
{
    const float* v     = (const float*)d_in[0];
    const float* g_w   = (const float*)d_in[1];
    const float* g_b   = (const float*)d_in[2];
    const float* th_w  = (const float*)d_in[3];
    const float* th_b  = (const float*)d_in[4];
    const float* ph_w  = (const float*)d_in[5];
    const float* ph_b  = (const float*)d_in[6];
    const float* W_w   = (const float*)d_in[7];
    const float* W_b   = (const float*)d_in[8];
    const float* gamma = (const float*)d_in[9];
    const float* beta  = (const float*)d_in[10];
    float* out = (float*)d_out;

    float *Theta, *Phi, *G, *M, *Q;
    cudaGetSymbolAddress((void**)&Theta, g_Theta);
    cudaGetSymbolAddress((void**)&Phi,   g_Phi);
    cudaGetSymbolAddress((void**)&G,     g_G);
    cudaGetSymbolAddress((void**)&M,     g_M);
    cudaGetSymbolAddress((void**)&Q,     g_Q);

    // 0. zero atomic scratch
    zero_scratch<<<(Bq * ICq * ICq + 255) / 256, 256>>>();

    // 1. Projections: X = v @ w^T + b   (32768 x 256, K=1024)
    {
        dim3 grid(ICq / 128, ROWS / 128, 1);
        sgemm_nt<<<grid, 256>>>(v, 0LL, g_w,  0LL, g_b,  G,     0LL, ROWS, ICq, Cq, 1.f);
        sgemm_nt<<<grid, 256>>>(v, 0LL, th_w, 0LL, th_b, Theta, 0LL, ROWS, ICq, Cq, 1.f);
        sgemm_nt<<<grid, 256>>>(v, 0LL, ph_w, 0LL, ph_b, Phi,   0LL, ROWS, ICq, Cq, 1.f);
    }

    // 2. M_b = Phi_b^T G_b / N  (split-K, atomics)
    {
        dim3 grid(ICq / 64, ICq / 64, Bq * 32);
        phiTg_kernel<<<grid, 256>>>(Phi, G);
    }

    // 3. Q_b[c][i] = sum_j W_w[c][j] * M_b[i][j]   (1024 x 256, K=256, batched)
    {
        dim3 grid(ICq / 128, Cq / 128, Bq);
        sgemm_nt<<<grid, 256>>>(W_w, 0LL,
                                M, (long long)ICq * ICq,
                                nullptr,
                                Q, (long long)Cq * ICq,
                                Cq, ICq, ICq, 1.f);
    }

    // 4. W_y = Theta_b @ Q_b^T + W_b  -> d_out  (4096 x 1024, K=256, batched)
    {
        dim3 grid(Cq / 128, Nq / 128, Bq);
        sgemm_nt<<<grid, 256>>>(Theta, (long long)Nq * ICq,
                                Q, (long long)Cq * ICq,
                                W_b,
                                out, (long long)Nq * Cq,
                                Nq, Cq, ICq, 1.f);
    }

    // 5. BN stats
    {
        dim3 grid(Cq / 128, ROWS / 256);
        bn_stats<<<grid, 128>>>(out);
    }

    // 6. normalize + residual
    bn_finalize<<<(ROWS * Cq / 4) / 256, 256>>>(out, v, gamma, beta);
}

// round 4
// speedup vs baseline: 2.1931x; 2.1931x over previous
#include <cuda_runtime.h>
#include <cstdint>

#define Bq    8
#define Nq    4096
#define Cq    1024
#define ICq   256
#define ROWS  (Bq * Nq)
#define EPSq  1e-5f

// ---------------------------------------------------------------------------
// Scratch
// ---------------------------------------------------------------------------
__device__ float g_Theta[ROWS * ICq];
__device__ float g_Phi[ROWS * ICq];
__device__ float g_G[ROWS * ICq];
__device__ float g_M[Bq * ICq * ICq];
__device__ float g_Q[Bq * Cq * ICq];
__device__ float g_sum[Cq];
__device__ float g_sumsq[Cq];

// ---------------------------------------------------------------------------
// Helpers
// ---------------------------------------------------------------------------
__device__ __forceinline__ uint32_t f2tf32(float x) {
    uint32_t r;
    asm("cvt.rna.tf32.f32 %0, %1;" : "=r"(r) : "f"(x));
    return r;
}

// m16n8k8 tf32 MMA (portable sm_80+ ISA; runs on the tensor pipe)
__device__ __forceinline__ void mma168(float* c, const uint32_t* a, const uint32_t* b) {
    asm volatile(
        "mma.sync.aligned.m16n8k8.row.col.f32.tf32.tf32.f32 "
        "{%0,%1,%2,%3}, {%4,%5,%6,%7}, {%8,%9}, {%0,%1,%2,%3};"
        : "+f"(c[0]), "+f"(c[1]), "+f"(c[2]), "+f"(c[3])
        : "r"(a[0]), "r"(a[1]), "r"(a[2]), "r"(a[3]), "r"(b[0]), "r"(b[1]));
}

#define LDAS 132   // 128 + 4 pad -> conflict-free fragment LDS

// ---------------------------------------------------------------------------
// tf32 mma.sync NT GEMM:
//   C[m][n] = sum_k A[m][k] * B[n][k] + bias[n]
// A: M x K row-major, B: N x K row-major, C: M x N (ldC), batched via z.
// Block tile 128x128, BK=16. 8 warps (2x4), warp tile 64x32.
// ---------------------------------------------------------------------------
__global__ __launch_bounds__(256, 2)
void tgemm(const float* __restrict__ A, long long sA,
           const float* __restrict__ B, long long sB,
           const float* __restrict__ bias,
           float* __restrict__ C, long long sC,
           int K, int ldC)
{
    __shared__ uint32_t As[2][16 * LDAS];
    __shared__ uint32_t Bs[2][16 * LDAS];

    const int tid  = threadIdx.x;
    const int lane = tid & 31;
    const int wid  = tid >> 5;
    const int wm   = wid & 1;          // 0..1 -> 64 rows each
    const int wn   = wid >> 1;         // 0..3 -> 32 cols each
    const int g    = lane >> 2;        // 0..7
    const int t    = lane & 3;         // 0..3

    A += (long long)blockIdx.z * sA;
    B += (long long)blockIdx.z * sB;
    C += (long long)blockIdx.z * sC;
    const long long m0 = (long long)blockIdx.x * 128;
    const long long n0 = (long long)blockIdx.y * 128;

    // global-load mapping: idx = tid + 256*i ; row = idx>>2 (0..127), kq = idx&3
    int lrow[2], lkq[2];
    const float* pA[2];
    const float* pB[2];
    #pragma unroll
    for (int i = 0; i < 2; i++) {
        int idx = tid + 256 * i;
        lrow[i] = idx >> 2;
        lkq[i]  = idx & 3;
        pA[i] = A + (m0 + lrow[i]) * (long long)K + lkq[i] * 4;
        pB[i] = B + (n0 + lrow[i]) * (long long)K + lkq[i] * 4;
    }

    float acc[4][4][4];
    #pragma unroll
    for (int a = 0; a < 4; a++)
        #pragma unroll
        for (int b = 0; b < 4; b++)
            #pragma unroll
            for (int r = 0; r < 4; r++) acc[a][b][r] = 0.f;

    float4 ra[2], rb[2];

    const int NCH = K >> 4;

    // prologue: chunk 0 -> stage 0
    #pragma unroll
    for (int i = 0; i < 2; i++) {
        ra[i] = *reinterpret_cast<const float4*>(pA[i]);
        rb[i] = *reinterpret_cast<const float4*>(pB[i]);
    }
    #pragma unroll
    for (int i = 0; i < 2; i++) {
        int base = lkq[i] * 4;
        As[0][(base + 0) * LDAS + lrow[i]] = f2tf32(ra[i].x);
        As[0][(base + 1) * LDAS + lrow[i]] = f2tf32(ra[i].y);
        As[0][(base + 2) * LDAS + lrow[i]] = f2tf32(ra[i].z);
        As[0][(base + 3) * LDAS + lrow[i]] = f2tf32(ra[i].w);
        Bs[0][(base + 0) * LDAS + lrow[i]] = f2tf32(rb[i].x);
        Bs[0][(base + 1) * LDAS + lrow[i]] = f2tf32(rb[i].y);
        Bs[0][(base + 2) * LDAS + lrow[i]] = f2tf32(rb[i].z);
        Bs[0][(base + 3) * LDAS + lrow[i]] = f2tf32(rb[i].w);
    }
    __syncthreads();

    for (int c = 0; c < NCH; ++c) {
        const int s = c & 1;
        if (c + 1 < NCH) {
            const int koff = (c + 1) << 4;
            #pragma unroll
            for (int i = 0; i < 2; i++) {
                ra[i] = *reinterpret_cast<const float4*>(pA[i] + koff);
                rb[i] = *reinterpret_cast<const float4*>(pB[i] + koff);
            }
        }

        // compute stage s
        #pragma unroll
        for (int kk = 0; kk < 16; kk += 8) {
            uint32_t af[4][4], bf[4][2];
            #pragma unroll
            for (int mt = 0; mt < 4; mt++) {
                int mr = wm * 64 + mt * 16 + g;
                af[mt][0] = As[s][(kk + t) * LDAS + mr];
                af[mt][1] = As[s][(kk + t) * LDAS + mr + 8];
                af[mt][2] = As[s][(kk + t + 4) * LDAS + mr];
                af[mt][3] = As[s][(kk + t + 4) * LDAS + mr + 8];
            }
            #pragma unroll
            for (int nt = 0; nt < 4; nt++) {
                int nc = wn * 32 + nt * 8 + g;
                bf[nt][0] = Bs[s][(kk + t) * LDAS + nc];
                bf[nt][1] = Bs[s][(kk + t + 4) * LDAS + nc];
            }
            #pragma unroll
            for (int mt = 0; mt < 4; mt++)
                #pragma unroll
                for (int nt = 0; nt < 4; nt++)
                    mma168(acc[mt][nt], af[mt], bf[nt]);
        }

        if (c + 1 < NCH) {
            const int s1 = (c + 1) & 1;
            #pragma unroll
            for (int i = 0; i < 2; i++) {
                int base = lkq[i] * 4;
                As[s1][(base + 0) * LDAS + lrow[i]] = f2tf32(ra[i].x);
                As[s1][(base + 1) * LDAS + lrow[i]] = f2tf32(ra[i].y);
                As[s1][(base + 2) * LDAS + lrow[i]] = f2tf32(ra[i].z);
                As[s1][(base + 3) * LDAS + lrow[i]] = f2tf32(ra[i].w);
                Bs[s1][(base + 0) * LDAS + lrow[i]] = f2tf32(rb[i].x);
                Bs[s1][(base + 1) * LDAS + lrow[i]] = f2tf32(rb[i].y);
                Bs[s1][(base + 2) * LDAS + lrow[i]] = f2tf32(rb[i].z);
                Bs[s1][(base + 3) * LDAS + lrow[i]] = f2tf32(rb[i].w);
            }
        }
        __syncthreads();
    }

    // epilogue
    #pragma unroll
    for (int mt = 0; mt < 4; mt++) {
        const long long row = m0 + wm * 64 + mt * 16 + g;
        #pragma unroll
        for (int nt = 0; nt < 4; nt++) {
            const long long col = n0 + wn * 32 + nt * 8 + 2 * t;
            float b0 = bias ? __ldg(&bias[col])     : 0.f;
            float b1 = bias ? __ldg(&bias[col + 1]) : 0.f;
            float2 o0 = make_float2(acc[mt][nt][0] + b0, acc[mt][nt][1] + b1);
            float2 o1 = make_float2(acc[mt][nt][2] + b0, acc[mt][nt][3] + b1);
            *reinterpret_cast<float2*>(&C[row * ldC + col])       = o0;
            *reinterpret_cast<float2*>(&C[(row + 8) * ldC + col]) = o1;
        }
    }
}

// ---------------------------------------------------------------------------
// phiTg via mma: M_b[i][j] = (1/N) sum_n Phi_b[n][i] * G_b[n][j]
// "A"[i][n] = Phi[n][i]  (i-contiguous in gmem -> coalesced transposed staging)
// Split-K: 8 chunks of 512 n-rows, atomicAdd epilogue into pre-zeroed g_M.
// grid (2, 2, Bq*8), 256 threads, same warp layout as tgemm.
// ---------------------------------------------------------------------------
__global__ __launch_bounds__(256, 2)
void phiTg_mma(const float* __restrict__ Phi, const float* __restrict__ G)
{
    __shared__ uint32_t As[2][16 * LDAS];
    __shared__ uint32_t Bs[2][16 * LDAS];

    const int tid  = threadIdx.x;
    const int lane = tid & 31;
    const int wid  = tid >> 5;
    const int wm   = wid & 1;
    const int wn   = wid >> 1;
    const int g    = lane >> 2;
    const int t    = lane & 3;

    const int batch = blockIdx.z >> 3;
    const int chunk = blockIdx.z & 7;
    const int i0 = blockIdx.x * 128;
    const int j0 = blockIdx.y * 128;

    const long long boff = (long long)batch * Nq * ICq;
    // staging mapping: idx = tid + 256*i -> n_loc = idx>>5 (0..15), iq = idx&31
    int nloc[2], iq[2];
    const float* pP[2];
    const float* pG[2];
    #pragma unroll
    for (int i = 0; i < 2; i++) {
        int idx = tid + 256 * i;
        nloc[i] = idx >> 5;
        iq[i]   = idx & 31;
        long long nbase = (long long)chunk * 512 + nloc[i];
        pP[i] = Phi + boff + nbase * ICq + i0 + iq[i] * 4;
        pG[i] = G   + boff + nbase * ICq + j0 + iq[i] * 4;
    }

    float acc[4][4][4];
    #pragma unroll
    for (int a = 0; a < 4; a++)
        #pragma unroll
        for (int b = 0; b < 4; b++)
            #pragma unroll
            for (int r = 0; r < 4; r++) acc[a][b][r] = 0.f;

    float4 ra[2], rb[2];
    const int NCH = 512 / 16;   // 32

    #pragma unroll
    for (int i = 0; i < 2; i++) {
        ra[i] = *reinterpret_cast<const float4*>(pP[i]);
        rb[i] = *reinterpret_cast<const float4*>(pG[i]);
    }
    #pragma unroll
    for (int i = 0; i < 2; i++) {
        int base = nloc[i] * LDAS + iq[i] * 4;
        As[0][base + 0] = f2tf32(ra[i].x); As[0][base + 1] = f2tf32(ra[i].y);
        As[0][base + 2] = f2tf32(ra[i].z); As[0][base + 3] = f2tf32(ra[i].w);
        Bs[0][base + 0] = f2tf32(rb[i].x); Bs[0][base + 1] = f2tf32(rb[i].y);
        Bs[0][base + 2] = f2tf32(rb[i].z); Bs[0][base + 3] = f2tf32(rb[i].w);
    }
    __syncthreads();

    for (int c = 0; c < NCH; ++c) {
        const int s = c & 1;
        if (c + 1 < NCH) {
            const long long koff = (long long)(c + 1) * 16 * ICq;
            #pragma unroll
            for (int i = 0; i < 2; i++) {
                ra[i] = *reinterpret_cast<const float4*>(pP[i] + koff);
                rb[i] = *reinterpret_cast<const float4*>(pG[i] + koff);
            }
        }

        #pragma unroll
        for (int kk = 0; kk < 16; kk += 8) {
            uint32_t af[4][4], bf[4][2];
            #pragma unroll
            for (int mt = 0; mt < 4; mt++) {
                int mr = wm * 64 + mt * 16 + g;
                af[mt][0] = As[s][(kk + t) * LDAS + mr];
                af[mt][1] = As[s][(kk + t) * LDAS + mr + 8];
                af[mt][2] = As[s][(kk + t + 4) * LDAS + mr];
                af[mt][3] = As[s][(kk + t + 4) * LDAS + mr + 8];
            }
            #pragma unroll
            for (int nt = 0; nt < 4; nt++) {
                int nc = wn * 32 + nt * 8 + g;
                bf[nt][0] = Bs[s][(kk + t) * LDAS + nc];
                bf[nt][1] = Bs[s][(kk + t + 4) * LDAS + nc];
            }
            #pragma unroll
            for (int mt = 0; mt < 4; mt++)
                #pragma unroll
                for (int nt = 0; nt < 4; nt++)
                    mma168(acc[mt][nt], af[mt], bf[nt]);
        }

        if (c + 1 < NCH) {
            const int s1 = (c + 1) & 1;
            #pragma unroll
            for (int i = 0; i < 2; i++) {
                int base = nloc[i] * LDAS + iq[i] * 4;
                As[s1][base + 0] = f2tf32(ra[i].x); As[s1][base + 1] = f2tf32(ra[i].y);
                As[s1][base + 2] = f2tf32(ra[i].z); As[s1][base + 3] = f2tf32(ra[i].w);
                Bs[s1][base + 0] = f2tf32(rb[i].x); Bs[s1][base + 1] = f2tf32(rb[i].y);
                Bs[s1][base + 2] = f2tf32(rb[i].z); Bs[s1][base + 3] = f2tf32(rb[i].w);
            }
        }
        __syncthreads();
    }

    float* Mb = g_M + (long long)batch * ICq * ICq;
    const float scale = 1.f / (float)Nq;
    #pragma unroll
    for (int mt = 0; mt < 4; mt++) {
        const int row = i0 + wm * 64 + mt * 16 + g;
        #pragma unroll
        for (int nt = 0; nt < 4; nt++) {
            const int col = j0 + wn * 32 + nt * 8 + 2 * t;
            atomicAdd(&Mb[row * ICq + col],           acc[mt][nt][0] * scale);
            atomicAdd(&Mb[row * ICq + col + 1],       acc[mt][nt][1] * scale);
            atomicAdd(&Mb[(row + 8) * ICq + col],     acc[mt][nt][2] * scale);
            atomicAdd(&Mb[(row + 8) * ICq + col + 1], acc[mt][nt][3] * scale);
        }
    }
}

// ---------------------------------------------------------------------------
// zero scratch / BN
// ---------------------------------------------------------------------------
__global__ void zero_scratch() {
    int i = blockIdx.x * blockDim.x + threadIdx.x;
    if (i < Bq * ICq * ICq) g_M[i] = 0.f;
    if (i < Cq) { g_sum[i] = 0.f; g_sumsq[i] = 0.f; }
}

__global__ __launch_bounds__(128)
void bn_stats(const float* __restrict__ Wy)
{
    const int ch = blockIdx.x * 128 + threadIdx.x;
    const long long r0 = (long long)blockIdx.y * 256;
    const float* p = Wy + r0 * Cq + ch;
    float s = 0.f, s2 = 0.f;
    #pragma unroll 8
    for (int r = 0; r < 256; r++) {
        float x = p[(long long)r * Cq];
        s += x; s2 += x * x;
    }
    atomicAdd(&g_sum[ch], s);
    atomicAdd(&g_sumsq[ch], s2);
}

__global__ __launch_bounds__(256)
void bn_finalize(float* __restrict__ out, const float* __restrict__ v,
                 const float* __restrict__ gamma, const float* __restrict__ beta)
{
    const long long i4 = (long long)blockIdx.x * 256 + threadIdx.x;
    const int c4 = (int)(i4 & (Cq / 4 - 1)) * 4;
    float4 w  = reinterpret_cast<float4*>(out)[i4];
    float4 vv = reinterpret_cast<const float4*>(v)[i4];
    const float inv = 1.f / (float)ROWS;
    float* wp = &w.x;
    const float* vp = &vv.x;
    #pragma unroll
    for (int c = 0; c < 4; c++) {
        float mean = g_sum[c4 + c] * inv;
        float var  = g_sumsq[c4 + c] * inv - mean * mean;
        float sc   = gamma[c4 + c] * rsqrtf(var + EPSq);
        wp[c] = (wp[c] - mean) * sc + beta[c4 + c] + vp[c];
    }
    reinterpret_cast<float4*>(out)[i4] = w;
}

// ---------------------------------------------------------------------------
// Launch
// ---------------------------------------------------------------------------
extern "C" void kernel_launch(void* const* d_in, const int* in_sizes, int n_in,
                              void* d_out, int out_size)
{
    const float* v     = (const float*)d_in[0];
    const float* g_w   = (const float*)d_in[1];
    const float* g_b   = (const float*)d_in[2];
    const float* th_w  = (const float*)d_in[3];
    const float* th_b  = (const float*)d_in[4];
    const float* ph_w  = (const float*)d_in[5];
    const float* ph_b  = (const float*)d_in[6];
    const float* W_w   = (const float*)d_in[7];
    const float* W_b   = (const float*)d_in[8];
    const float* gamma = (const float*)d_in[9];
    const float* beta  = (const float*)d_in[10];
    float* out = (float*)d_out;

    float *Theta, *Phi, *G, *M, *Q;
    cudaGetSymbolAddress((void**)&Theta, g_Theta);
    cudaGetSymbolAddress((void**)&Phi,   g_Phi);
    cudaGetSymbolAddress((void**)&G,     g_G);
    cudaGetSymbolAddress((void**)&M,     g_M);
    cudaGetSymbolAddress((void**)&Q,     g_Q);

    zero_scratch<<<(Bq * ICq * ICq + 255) / 256, 256>>>();

    // 1. Projections: (32768 x 256, K=1024)
    {
        dim3 grid(ROWS / 128, ICq / 128, 1);   // (256, 2)
        tgemm<<<grid, 256>>>(v, 0LL, g_w,  0LL, g_b,  G,     0LL, Cq, ICq);
        tgemm<<<grid, 256>>>(v, 0LL, th_w, 0LL, th_b, Theta, 0LL, Cq, ICq);
        tgemm<<<grid, 256>>>(v, 0LL, ph_w, 0LL, ph_b, Phi,   0LL, Cq, ICq);
    }

    // 2. M_b = Phi_b^T G_b / N  (mma + split-K atomics)
    {
        dim3 grid(ICq / 128, ICq / 128, Bq * 8);   // (2, 2, 64)
        phiTg_mma<<<grid, 256>>>(Phi, G);
    }

    // 3. Q_b[c][i] = sum_j W_w[c][j] * M_b[i][j]  (1024 x 256, K=256)
    {
        dim3 grid(Cq / 128, ICq / 128, Bq);        // (8, 2, 8)
        tgemm<<<grid, 256>>>(W_w, 0LL,
                             M, (long long)ICq * ICq,
                             nullptr,
                             Q, (long long)Cq * ICq,
                             ICq, ICq);
    }

    // 4. W_y = Theta_b @ Q_b^T + W_b  (4096 x 1024, K=256)
    {
        dim3 grid(Nq / 128, Cq / 128, Bq);         // (32, 8, 8)
        tgemm<<<grid, 256>>>(Theta, (long long)Nq * ICq,
                             Q, (long long)Cq * ICq,
                             W_b,
                             out, (long long)Nq * Cq,
                             ICq, Cq);
    }

    // 5. BN stats
    {
        dim3 grid(Cq / 128, ROWS / 256);
        bn_stats<<<grid, 128>>>(out);
    }

    // 6. normalize + residual
    bn_finalize<<<(ROWS * Cq / 4) / 256, 256>>>(out, v, gamma, beta);
}

// round 5
// speedup vs baseline: 2.6631x; 1.2143x over previous
#include <cuda_runtime.h>
#include <cstdint>

#define Bq    8
#define Nq    4096
#define Cq    1024
#define ICq   256
#define ROWS  (Bq * Nq)
#define EPSq  1e-5f

// ---------------------------------------------------------------------------
// Scratch (device globals)
// ---------------------------------------------------------------------------
__device__ float g_vr[ROWS * Cq];          // tf32-rounded v (128 MB)
__device__ float g_Theta[ROWS * ICq];
__device__ float g_Phi[ROWS * ICq];
__device__ float g_G[ROWS * ICq];
__device__ float g_M[Bq * ICq * ICq];
__device__ float g_Q[Bq * Cq * ICq];
__device__ float g_wr[4 * ICq * Cq];       // rounded g_w, theta_w, phi_w, W_w
__device__ float g_sum[Cq];
__device__ float g_sumsq[Cq];

// ---------------------------------------------------------------------------
// Helpers
// ---------------------------------------------------------------------------
__device__ __forceinline__ uint32_t smem_u32(const void* p) {
    uint32_t a;
    asm("{ .reg .u64 t; cvta.to.shared.u64 t, %1; cvt.u32.u64 %0, t; }"
        : "=r"(a) : "l"(p));
    return a;
}
__device__ __forceinline__ uint32_t f2tf32(float x) {
    uint32_t r;
    asm("cvt.rna.tf32.f32 %0, %1;" : "=r"(r) : "f"(x));
    return r;
}
__device__ __forceinline__ float rndf(float x) { return __uint_as_float(f2tf32(x)); }

__device__ __forceinline__ void mma168(float* c, const uint32_t* a, const uint32_t* b) {
    asm volatile(
        "mma.sync.aligned.m16n8k8.row.col.f32.tf32.tf32.f32 "
        "{%0,%1,%2,%3}, {%4,%5,%6,%7}, {%8,%9}, {%0,%1,%2,%3};"
        : "+f"(c[0]), "+f"(c[1]), "+f"(c[2]), "+f"(c[3])
        : "r"(a[0]), "r"(a[1]), "r"(a[2]), "r"(a[3]), "r"(b[0]), "r"(b[1]));
}

#define CP_ASYNC(dst, src) \
    asm volatile("cp.async.cg.shared.global [%0], [%1], 16;" :: "r"(dst), "l"(src))
#define CP_COMMIT() asm volatile("cp.async.commit_group;" ::: "memory")
#define CP_WAIT1()  asm volatile("cp.async.wait_group 1;" ::: "memory")

// ---------------------------------------------------------------------------
// tf32 mma NT GEMM with cp.async 3-stage pipeline.
//   C[m][n] = sum_k A[m][k]*B[n][k] + bias[n]
// Inputs MUST be pre-rounded to tf32. Block tile 128x128, BK=16.
// smem: [row][k] stride 20 words (conflict-free fragment LDS).
// Stage = A(128x20w) + B(128x20w) = 20480 B; 3 stages = 61440 B dynamic.
// ---------------------------------------------------------------------------
#define TG_STAGE_B   20480
#define TG_STAGE_W   5120
#define TG_SMEM      (3 * TG_STAGE_B)

template<bool ROUND, bool STATS>
__global__ __launch_bounds__(256, 2)
void tgemm(const float* __restrict__ A, long long sA,
           const float* __restrict__ B, long long sB,
           const float* __restrict__ bias,
           float* __restrict__ C, long long sC,
           int K, int ldC)
{
    extern __shared__ char smem[];
    const uint32_t sb = smem_u32(smem);
    const uint32_t* SW = reinterpret_cast<const uint32_t*>(smem);

    const int tid  = threadIdx.x;
    const int lane = tid & 31;
    const int wid  = tid >> 5;
    const int wm   = wid & 1;
    const int wn   = wid >> 1;
    const int g    = lane >> 2;
    const int t    = lane & 3;

    A += (long long)blockIdx.z * sA;
    B += (long long)blockIdx.z * sB;
    C += (long long)blockIdx.z * sC;
    const long long m0 = (long long)blockIdx.x * 128;
    const long long n0 = (long long)blockIdx.y * 128;

    // cp.async mapping: idx in [0,512): row = idx>>2, seg = idx&3 (16B each)
    const int r0 = tid >> 2, sg = tid & 3;
    const float* srcA0 = A + (m0 + r0) * (long long)K + sg * 4;
    const float* srcA1 = A + (m0 + r0 + 64) * (long long)K + sg * 4;
    const float* srcB0 = B + (n0 + r0) * (long long)K + sg * 4;
    const float* srcB1 = B + (n0 + r0 + 64) * (long long)K + sg * 4;
    const uint32_t dst0 = r0 * 80 + sg * 16;
    const uint32_t dst1 = (r0 + 64) * 80 + sg * 16;

    const int NCH = K >> 4;

#define TG_LOAD(c, st) do {                                   \
        uint32_t b_ = sb + (st) * TG_STAGE_B;                 \
        int k_ = (c) << 4;                                    \
        CP_ASYNC(b_ + dst0,         srcA0 + k_);              \
        CP_ASYNC(b_ + dst1,         srcA1 + k_);              \
        CP_ASYNC(b_ + 10240 + dst0, srcB0 + k_);              \
        CP_ASYNC(b_ + 10240 + dst1, srcB1 + k_);              \
    } while (0)

    TG_LOAD(0, 0); CP_COMMIT();
    TG_LOAD(1, 1); CP_COMMIT();

    float acc[4][4][4];
    #pragma unroll
    for (int a = 0; a < 4; a++)
        #pragma unroll
        for (int b = 0; b < 4; b++)
            #pragma unroll
            for (int r = 0; r < 4; r++) acc[a][b][r] = 0.f;

    for (int c = 0; c < NCH; ++c) {
        const int st = c % 3;
        CP_WAIT1();
        __syncthreads();
        if (c + 2 < NCH) { TG_LOAD(c + 2, (c + 2) % 3); }
        CP_COMMIT();

        const uint32_t* As = SW + st * TG_STAGE_W;
        const uint32_t* Bs = As + 2560;

        #pragma unroll
        for (int kk = 0; kk < 16; kk += 8) {
            uint32_t af[4][4], bf[4][2];
            #pragma unroll
            for (int mt = 0; mt < 4; mt++) {
                const int mr = wm * 64 + mt * 16 + g;
                af[mt][0] = As[mr * 20 + kk + t];
                af[mt][1] = As[(mr + 8) * 20 + kk + t];
                af[mt][2] = As[mr * 20 + kk + t + 4];
                af[mt][3] = As[(mr + 8) * 20 + kk + t + 4];
            }
            #pragma unroll
            for (int nt = 0; nt < 4; nt++) {
                const int nc = wn * 32 + nt * 8 + g;
                bf[nt][0] = Bs[nc * 20 + kk + t];
                bf[nt][1] = Bs[nc * 20 + kk + t + 4];
            }
            #pragma unroll
            for (int mt = 0; mt < 4; mt++)
                #pragma unroll
                for (int nt = 0; nt < 4; nt++)
                    mma168(acc[mt][nt], af[mt], bf[nt]);
        }
    }
#undef TG_LOAD

    // ---- epilogue ----
    float* ssum = nullptr; float* ssq = nullptr;
    if (STATS) {
        __syncthreads();                       // stage data dead; reuse smem
        ssum = (float*)smem; ssq = ssum + 128;
        if (tid < 128) { ssum[tid] = 0.f; ssq[tid] = 0.f; }
        __syncthreads();
    }

    float colS[4][2], colS2[4][2];
    #pragma unroll
    for (int nt = 0; nt < 4; nt++) { colS[nt][0]=colS[nt][1]=colS2[nt][0]=colS2[nt][1]=0.f; }

    #pragma unroll
    for (int mt = 0; mt < 4; mt++) {
        const long long row = m0 + wm * 64 + mt * 16 + g;
        #pragma unroll
        for (int nt = 0; nt < 4; nt++) {
            const long long col = n0 + wn * 32 + nt * 8 + 2 * t;
            const float b0 = bias ? __ldg(&bias[col])     : 0.f;
            const float b1 = bias ? __ldg(&bias[col + 1]) : 0.f;
            float v00 = acc[mt][nt][0] + b0, v01 = acc[mt][nt][1] + b1;
            float v10 = acc[mt][nt][2] + b0, v11 = acc[mt][nt][3] + b1;
            if (STATS) {
                colS[nt][0]  += v00 + v10;        colS[nt][1]  += v01 + v11;
                colS2[nt][0] += v00*v00 + v10*v10; colS2[nt][1] += v01*v01 + v11*v11;
            }
            float2 o0, o1;
            if (ROUND) {
                o0 = make_float2(rndf(v00), rndf(v01));
                o1 = make_float2(rndf(v10), rndf(v11));
            } else {
                o0 = make_float2(v00, v01);
                o1 = make_float2(v10, v11);
            }
            *reinterpret_cast<float2*>(&C[row * ldC + col])       = o0;
            *reinterpret_cast<float2*>(&C[(row + 8) * ldC + col]) = o1;
        }
    }

    if (STATS) {
        #pragma unroll
        for (int nt = 0; nt < 4; nt++) {
            const int cl = wn * 32 + nt * 8 + 2 * t;
            atomicAdd(&ssum[cl],     colS[nt][0]);
            atomicAdd(&ssum[cl + 1], colS[nt][1]);
            atomicAdd(&ssq[cl],      colS2[nt][0]);
            atomicAdd(&ssq[cl + 1],  colS2[nt][1]);
        }
        __syncthreads();
        if (tid < 128) {
            atomicAdd(&g_sum[n0 + tid],   ssum[tid]);
            atomicAdd(&g_sumsq[n0 + tid], ssq[tid]);
        }
    }
}

// ---------------------------------------------------------------------------
// phiTg: M_b[i][j] = (1/N) sum_n Phi_b[n][i] * G_b[n][j]
// smem layout [k=n][i] stride 136 words (conflict-free: bank = 8t+g).
// Split-K: 8 chunks of 512 n; block tile 128x128; NCH=32 (BK=16).
// Stage = 2 * 16 * 136 * 4 = 17408 B; 3 stages = 52224 B.
// ---------------------------------------------------------------------------
#define PH_STAGE_B 17408
#define PH_STAGE_W 4352
#define PH_SMEM    (3 * PH_STAGE_B)

__global__ __launch_bounds__(256, 2)
void phiTg(const float* __restrict__ Phi, const float* __restrict__ G)
{
    extern __shared__ char smem[];
    const uint32_t sb = smem_u32(smem);
    const uint32_t* SW = reinterpret_cast<const uint32_t*>(smem);

    const int tid  = threadIdx.x;
    const int lane = tid & 31;
    const int wid  = tid >> 5;
    const int wm   = wid & 1;
    const int wn   = wid >> 1;
    const int g    = lane >> 2;
    const int t    = lane & 3;

    const int batch = blockIdx.z >> 3;
    const int chunk = blockIdx.z & 7;
    const int i0 = blockIdx.x * 128;
    const int j0 = blockIdx.y * 128;

    const long long base = (long long)batch * Nq * ICq + (long long)chunk * 512 * ICq;

    // cp.async: idx in [0,512): nrow = idx>>5 (0..15), seg = idx&31
    const int nr = tid >> 5, sg = tid & 31;
    const float* srcP0 = Phi + base + (long long)nr * ICq + i0 + sg * 4;
    const float* srcP1 = Phi + base + (long long)(nr + 8) * ICq + i0 + sg * 4;
    const float* srcG0 = G   + base + (long long)nr * ICq + j0 + sg * 4;
    const float* srcG1 = G   + base + (long long)(nr + 8) * ICq + j0 + sg * 4;
    const uint32_t dst0 = nr * 544 + sg * 16;
    const uint32_t dst1 = (nr + 8) * 544 + sg * 16;

    const int NCH = 32;

#define PH_LOAD(c, st) do {                                   \
        uint32_t b_ = sb + (st) * PH_STAGE_B;                 \
        long long k_ = (long long)(c) * 16 * ICq;             \
        CP_ASYNC(b_ + dst0,        srcP0 + k_);               \
        CP_ASYNC(b_ + dst1,        srcP1 + k_);               \
        CP_ASYNC(b_ + 8704 + dst0, srcG0 + k_);               \
        CP_ASYNC(b_ + 8704 + dst1, srcG1 + k_);               \
    } while (0)

    PH_LOAD(0, 0); CP_COMMIT();
    PH_LOAD(1, 1); CP_COMMIT();

    float acc[4][4][4];
    #pragma unroll
    for (int a = 0; a < 4; a++)
        #pragma unroll
        for (int b = 0; b < 4; b++)
            #pragma unroll
            for (int r = 0; r < 4; r++) acc[a][b][r] = 0.f;

    for (int c = 0; c < NCH; ++c) {
        const int st = c % 3;
        CP_WAIT1();
        __syncthreads();
        if (c + 2 < NCH) { PH_LOAD(c + 2, (c + 2) % 3); }
        CP_COMMIT();

        const uint32_t* As = SW + st * PH_STAGE_W;
        const uint32_t* Bs = As + 2176;

        #pragma unroll
        for (int kk = 0; kk < 16; kk += 8) {
            uint32_t af[4][4], bf[4][2];
            #pragma unroll
            for (int mt = 0; mt < 4; mt++) {
                const int ir = wm * 64 + mt * 16 + g;
                af[mt][0] = As[(kk + t) * 136 + ir];
                af[mt][1] = As[(kk + t) * 136 + ir + 8];
                af[mt][2] = As[(kk + t + 4) * 136 + ir];
                af[mt][3] = As[(kk + t + 4) * 136 + ir + 8];
            }
            #pragma unroll
            for (int nt = 0; nt < 4; nt++) {
                const int jc = wn * 32 + nt * 8 + g;
                bf[nt][0] = Bs[(kk + t) * 136 + jc];
                bf[nt][1] = Bs[(kk + t + 4) * 136 + jc];
            }
            #pragma unroll
            for (int mt = 0; mt < 4; mt++)
                #pragma unroll
                for (int nt = 0; nt < 4; nt++)
                    mma168(acc[mt][nt], af[mt], bf[nt]);
        }
    }
#undef PH_LOAD

    float* Mb = g_M + (long long)batch * ICq * ICq;
    const float scale = 1.f / (float)Nq;
    #pragma unroll
    for (int mt = 0; mt < 4; mt++) {
        const int row = i0 + wm * 64 + mt * 16 + g;
        #pragma unroll
        for (int nt = 0; nt < 4; nt++) {
            const int col = j0 + wn * 32 + nt * 8 + 2 * t;
            atomicAdd(&Mb[row * ICq + col],           acc[mt][nt][0] * scale);
            atomicAdd(&Mb[row * ICq + col + 1],       acc[mt][nt][1] * scale);
            atomicAdd(&Mb[(row + 8) * ICq + col],     acc[mt][nt][2] * scale);
            atomicAdd(&Mb[(row + 8) * ICq + col + 1], acc[mt][nt][3] * scale);
        }
    }
}

// ---------------------------------------------------------------------------
// tf32 rounding pass (float4 granularity)
// ---------------------------------------------------------------------------
__global__ __launch_bounds__(256)
void round_buf(const float4* __restrict__ src, float4* __restrict__ dst, int n4)
{
    int i = blockIdx.x * 256 + threadIdx.x;
    if (i < n4) {
        float4 x = src[i];
        x.x = rndf(x.x); x.y = rndf(x.y); x.z = rndf(x.z); x.w = rndf(x.w);
        dst[i] = x;
    }
}

__global__ void zero_scratch() {
    int i = blockIdx.x * blockDim.x + threadIdx.x;
    if (i < Bq * ICq * ICq) g_M[i] = 0.f;
    if (i < Cq) { g_sum[i] = 0.f; g_sumsq[i] = 0.f; }
}

__global__ __launch_bounds__(256)
void bn_finalize(float* __restrict__ out, const float* __restrict__ v,
                 const float* __restrict__ gamma, const float* __restrict__ beta)
{
    const long long i4 = (long long)blockIdx.x * 256 + threadIdx.x;
    const int c4 = (int)(i4 & (Cq / 4 - 1)) * 4;
    float4 w  = reinterpret_cast<float4*>(out)[i4];
    float4 vv = reinterpret_cast<const float4*>(v)[i4];
    const float inv = 1.f / (float)ROWS;
    float* wp = &w.x;
    const float* vp = &vv.x;
    #pragma unroll
    for (int c = 0; c < 4; c++) {
        float mean = g_sum[c4 + c] * inv;
        float var  = g_sumsq[c4 + c] * inv - mean * mean;
        float sc   = gamma[c4 + c] * rsqrtf(var + EPSq);
        wp[c] = (wp[c] - mean) * sc + beta[c4 + c] + vp[c];
    }
    reinterpret_cast<float4*>(out)[i4] = w;
}

// ---------------------------------------------------------------------------
// Launch
// ---------------------------------------------------------------------------
extern "C" void kernel_launch(void* const* d_in, const int* in_sizes, int n_in,
                              void* d_out, int out_size)
{
    const float* v     = (const float*)d_in[0];
    const float* g_w   = (const float*)d_in[1];
    const float* g_b   = (const float*)d_in[2];
    const float* th_w  = (const float*)d_in[3];
    const float* th_b  = (const float*)d_in[4];
    const float* ph_w  = (const float*)d_in[5];
    const float* ph_b  = (const float*)d_in[6];
    const float* W_w   = (const float*)d_in[7];
    const float* W_b   = (const float*)d_in[8];
    const float* gamma = (const float*)d_in[9];
    const float* beta  = (const float*)d_in[10];
    float* out = (float*)d_out;

    float *vr, *Theta, *Phi, *G, *M, *Q, *wr;
    cudaGetSymbolAddress((void**)&vr,    g_vr);
    cudaGetSymbolAddress((void**)&Theta, g_Theta);
    cudaGetSymbolAddress((void**)&Phi,   g_Phi);
    cudaGetSymbolAddress((void**)&G,     g_G);
    cudaGetSymbolAddress((void**)&M,     g_M);
    cudaGetSymbolAddress((void**)&Q,     g_Q);
    cudaGetSymbolAddress((void**)&wr,    g_wr);

    cudaFuncSetAttribute(tgemm<true, false>,
                         cudaFuncAttributeMaxDynamicSharedMemorySize, TG_SMEM);
    cudaFuncSetAttribute(tgemm<false, true>,
                         cudaFuncAttributeMaxDynamicSharedMemorySize, TG_SMEM);
    cudaFuncSetAttribute(phiTg,
                         cudaFuncAttributeMaxDynamicSharedMemorySize, PH_SMEM);

    const int WK = ICq * Cq;  // 262144 elems per weight matrix

    zero_scratch<<<(Bq * ICq * ICq + 255) / 256, 256>>>();

    // Pre-round inputs to tf32
    round_buf<<<(ROWS * Cq / 4 + 255) / 256, 256>>>((const float4*)v, (float4*)vr, ROWS * Cq / 4);
    round_buf<<<(WK / 4 + 255) / 256, 256>>>((const float4*)g_w,  (float4*)(wr + 0 * WK), WK / 4);
    round_buf<<<(WK / 4 + 255) / 256, 256>>>((const float4*)th_w, (float4*)(wr + 1 * WK), WK / 4);
    round_buf<<<(WK / 4 + 255) / 256, 256>>>((const float4*)ph_w, (float4*)(wr + 2 * WK), WK / 4);
    round_buf<<<(WK / 4 + 255) / 256, 256>>>((const float4*)W_w,  (float4*)(wr + 3 * WK), WK / 4);

    // 1. Projections (32768 x 256, K=1024) — outputs rounded
    {
        dim3 grid(ROWS / 128, ICq / 128, 1);
        tgemm<true, false><<<grid, 256, TG_SMEM>>>(vr, 0LL, wr + 0 * WK, 0LL, g_b,  G,     0LL, Cq, ICq);
        tgemm<true, false><<<grid, 256, TG_SMEM>>>(vr, 0LL, wr + 1 * WK, 0LL, th_b, Theta, 0LL, Cq, ICq);
        tgemm<true, false><<<grid, 256, TG_SMEM>>>(vr, 0LL, wr + 2 * WK, 0LL, ph_b, Phi,   0LL, Cq, ICq);
    }

    // 2. M_b = Phi_b^T G_b / N  (split-K atomics), then round M in place
    {
        dim3 grid(ICq / 128, ICq / 128, Bq * 8);
        phiTg<<<grid, 256, PH_SMEM>>>(Phi, G);
        round_buf<<<(Bq * ICq * ICq / 4 + 255) / 256, 256>>>((const float4*)M, (float4*)M, Bq * ICq * ICq / 4);
    }

    // 3. Q_b = W_w @ M_b^T  (1024 x 256, K=256) — output rounded
    {
        dim3 grid(Cq / 128, ICq / 128, Bq);
        tgemm<true, false><<<grid, 256, TG_SMEM>>>(wr + 3 * WK, 0LL,
                                                   M, (long long)ICq * ICq,
                                                   nullptr,
                                                   Q, (long long)Cq * ICq,
                                                   ICq, ICq);
    }

    // 4. W_y = Theta_b @ Q_b^T + W_b  (4096 x 1024, K=256) + fused BN stats
    {
        dim3 grid(Nq / 128, Cq / 128, Bq);
        tgemm<false, true><<<grid, 256, TG_SMEM>>>(Theta, (long long)Nq * ICq,
                                                   Q, (long long)Cq * ICq,
                                                   W_b,
                                                   out, (long long)Nq * Cq,
                                                   ICq, Cq);
    }

    // 5. normalize + residual
    bn_finalize<<<(ROWS * Cq / 4) / 256, 256>>>(out, v, gamma, beta);
}